// round 2
// baseline (speedup 1.0000x reference)
#include <cuda_runtime.h>
#include <math.h>

#define INC 64
#define HID 16
#define BATCHES 8
#define NMAX 300032   // N=300000 (+ pad row)

// ---- scratch (no allocations allowed) ----
__device__ float    g_segsum[BATCHES * INC];
__device__ unsigned g_segmax[BATCHES * INC];   // order-encoded float
__device__ float    g_count[BATCHES];
__device__ float    g_gate[BATCHES * INC];
__device__ float2   g_sm[NMAX];                // (mean, max) per point, + zero pad row
__device__ float    g_sig[NMAX];               // spatial sigmoid per point

__device__ __forceinline__ unsigned encode_ord(float f) {
    unsigned b = __float_as_uint(f);
    return (b & 0x80000000u) ? ~b : (b ^ 0x80000000u);
}
__device__ __forceinline__ float decode_ord(unsigned u) {
    unsigned b = (u & 0x80000000u) ? (u ^ 0x80000000u) : ~u;
    return __uint_as_float(b);
}

// ---- K0: init scratch ----
__global__ void k_init(int n) {
    int t = threadIdx.x;
    if (t < BATCHES * INC) {
        g_segsum[t] = 0.f;
        g_segmax[t] = encode_ord(-INFINITY);
    }
    if (t < BATCHES) g_count[t] = 0.f;
    if (t == 0) g_sm[n] = make_float2(0.f, 0.f);  // pad row for missing neighbors
}

// ---- K1: per-batch segment sum/max of F, float4 path ----
// 256 threads: 16 channel-quads x 16 row-lanes. batch_idx sorted -> rare flushes.
__global__ void k_seg(const float* __restrict__ F, const int* __restrict__ bidx,
                      int n, int chunk) {
    int q     = threadIdx.x & 15;   // channel quad (4 channels)
    int rlane = threadIdx.x >> 4;   // 0..15 row lanes
    int start = blockIdx.x * chunk;
    int end   = min(start + chunk, n);

    float4 sum = make_float4(0.f, 0.f, 0.f, 0.f);
    float4 mx  = make_float4(-INFINITY, -INFINITY, -INFINITY, -INFINITY);
    float cnt = 0.f;
    int cur = -1;

    for (int r = start + rlane; r < end; r += 16) {
        int b = bidx[r];
        if (b != cur) {
            if (cur >= 0) {
                float* ss = &g_segsum[cur * INC + q * 4];
                unsigned* sx = &g_segmax[cur * INC + q * 4];
                atomicAdd(ss + 0, sum.x); atomicAdd(ss + 1, sum.y);
                atomicAdd(ss + 2, sum.z); atomicAdd(ss + 3, sum.w);
                atomicMax(sx + 0, encode_ord(mx.x)); atomicMax(sx + 1, encode_ord(mx.y));
                atomicMax(sx + 2, encode_ord(mx.z)); atomicMax(sx + 3, encode_ord(mx.w));
                if (q == 0) atomicAdd(&g_count[cur], cnt);
            }
            cur = b;
            sum = make_float4(0.f, 0.f, 0.f, 0.f);
            mx  = make_float4(-INFINITY, -INFINITY, -INFINITY, -INFINITY);
            cnt = 0.f;
        }
        float4 v = ((const float4*)(F + (long)r * INC))[q];
        sum.x += v.x; sum.y += v.y; sum.z += v.z; sum.w += v.w;
        mx.x = fmaxf(mx.x, v.x); mx.y = fmaxf(mx.y, v.y);
        mx.z = fmaxf(mx.z, v.z); mx.w = fmaxf(mx.w, v.w);
        cnt += 1.f;
    }
    if (cur >= 0) {
        float* ss = &g_segsum[cur * INC + q * 4];
        unsigned* sx = &g_segmax[cur * INC + q * 4];
        atomicAdd(ss + 0, sum.x); atomicAdd(ss + 1, sum.y);
        atomicAdd(ss + 2, sum.z); atomicAdd(ss + 3, sum.w);
        atomicMax(sx + 0, encode_ord(mx.x)); atomicMax(sx + 1, encode_ord(mx.y));
        atomicMax(sx + 2, encode_ord(mx.z)); atomicMax(sx + 3, encode_ord(mx.w));
        if (q == 0) atomicAdd(&g_count[cur], cnt);
    }
}

// ---- K2: tiny shared MLP -> per-batch channel gate (1 block) ----
__global__ void k_gate(const float* __restrict__ W1, const float* __restrict__ b1,
                       const float* __restrict__ W2, const float* __restrict__ b2) {
    __shared__ float h1a[BATCHES][HID], h1m[BATCHES][HID];
    int t = threadIdx.x;  // 128 threads
    if (t < BATCHES * HID) {
        int b = t / HID, j = t % HID;
        float sa = b1[j], sm = b1[j];
        float inv = 1.f / g_count[b];
        for (int c = 0; c < INC; c++) {
            float w    = W1[c * HID + j];
            float mean = g_segsum[b * INC + c] * inv;
            float mxv  = decode_ord(g_segmax[b * INC + c]);
            sa += mean * w;
            sm += mxv * w;
        }
        h1a[b][j] = fmaxf(sa, 0.f);
        h1m[b][j] = fmaxf(sm, 0.f);
    }
    __syncthreads();
    for (int t2 = t; t2 < BATCHES * INC; t2 += 128) {
        int b = t2 / INC, c = t2 % INC;
        float s = 2.f * b2[c];
        for (int j = 0; j < HID; j++)
            s += (h1a[b][j] + h1m[b][j]) * W2[j * INC + c];
        g_gate[t2] = 1.f / (1.f + expf(-s));
    }
}

// ---- K3: half-warp-per-row, float4: z = F*gate ; sm = (mean_c z, max_c z) ----
__global__ void k_sm(const float* __restrict__ F, const int* __restrict__ bidx, int n) {
    int gtid   = blockIdx.x * blockDim.x + threadIdx.x;
    int hw     = gtid >> 4;             // half-warp id
    int lane16 = threadIdx.x & 15;
    int nhw    = (gridDim.x * blockDim.x) >> 4;
    for (int r = hw; r < n; r += nhw) {
        int b = bidx[r];
        float4 f = ((const float4*)(F + (long)r * INC))[lane16];
        float4 g = ((const float4*)(g_gate + b * INC))[lane16];
        float z0 = f.x * g.x, z1 = f.y * g.y, z2 = f.z * g.z, z3 = f.w * g.w;
        float s = (z0 + z1) + (z2 + z3);
        float m = fmaxf(fmaxf(z0, z1), fmaxf(z2, z3));
        #pragma unroll
        for (int o = 8; o > 0; o >>= 1) {
            s += __shfl_xor_sync(0xffffffffu, s, o);
            m = fmaxf(m, __shfl_xor_sync(0xffffffffu, m, o));
        }
        if (lane16 == 0) g_sm[r] = make_float2(s * (1.f / 64.f), m);
    }
}

// ---- K4: thread-per-point 27-neighbor gather conv -> sigmoid (g_sm is L2-resident) ----
__global__ void k_conv(const int* __restrict__ nbr, const float* __restrict__ conv_w,
                       int n) {
    __shared__ float sw[54];
    if (threadIdx.x < 54) sw[threadIdx.x] = conv_w[threadIdx.x];
    __syncthreads();

    int r = blockIdx.x * blockDim.x + threadIdx.x;
    if (r >= n) return;
    const int* nb = nbr + (long)r * 27;
    float p = 0.f;
    #pragma unroll
    for (int k = 0; k < 27; k++) {
        float2 s = g_sm[nb[k]];
        p += s.x * sw[2 * k] + s.y * sw[2 * k + 1];
    }
    g_sig[r] = 1.f / (1.f + expf(-p));
}

// ---- K5: pure float4 stream: out = F * gate[bidx] * sig ----
__global__ void k_mul(const float* __restrict__ F, const int* __restrict__ bidx,
                      float* __restrict__ out, int n) {
    long total = (long)n * (INC / 4);
    long i = (long)blockIdx.x * blockDim.x + threadIdx.x;
    if (i >= total) return;
    int r  = (int)(i >> 4);
    int c4 = (int)(i & 15);
    float4 f = ((const float4*)F)[i];
    int b = bidx[r];
    float4 g = ((const float4*)g_gate)[b * 16 + c4];
    float sg = g_sig[r];
    float4 o;
    o.x = f.x * g.x * sg; o.y = f.y * g.y * sg;
    o.z = f.z * g.z * sg; o.w = f.w * g.w * sg;
    ((float4*)out)[i] = o;
}

extern "C" void kernel_launch(void* const* d_in, const int* in_sizes, int n_in,
                              void* d_out, int out_size) {
    const float* F      = (const float*)d_in[0];
    const int*   bidx   = (const int*)d_in[1];
    const int*   nbr    = (const int*)d_in[2];
    const float* W1     = (const float*)d_in[3];
    const float* b1     = (const float*)d_in[4];
    const float* W2     = (const float*)d_in[5];
    const float* b2     = (const float*)d_in[6];
    const float* conv_w = (const float*)d_in[7];
    float* out = (float*)d_out;
    int n = in_sizes[1];   // batch_idx length = N

    k_init<<<1, 512>>>(n);

    const int chunk = 256;
    k_seg<<<(n + chunk - 1) / chunk, 256>>>(F, bidx, n, chunk);

    k_gate<<<1, 128>>>(W1, b1, W2, b2);

    k_sm<<<1184, 256>>>(F, bidx, n);

    k_conv<<<(n + 255) / 256, 256>>>(nbr, conv_w, n);

    long total4 = (long)n * (INC / 4);
    k_mul<<<(int)((total4 + 255) / 256), 256>>>(F, bidx, out, n);
}

// round 3
// speedup vs baseline: 1.1718x; 1.1718x over previous
#include <cuda_runtime.h>
#include <math.h>

#define INC 64
#define HID 16
#define BATCHES 8
#define NMAX 300032   // N=300000 (+ pad row)

// ---- scratch (no allocations allowed) ----
__device__ float    g_segsum[BATCHES * INC];
__device__ unsigned g_segmax[BATCHES * INC];   // order-encoded float
__device__ float    g_count[BATCHES];
__device__ float    g_gate[BATCHES * INC];
__device__ float2   g_sm[NMAX];                // (mean, max) per point, + zero pad row
__device__ float    g_sig[NMAX];               // spatial sigmoid per point

__device__ __forceinline__ unsigned encode_ord(float f) {
    unsigned b = __float_as_uint(f);
    return (b & 0x80000000u) ? ~b : (b ^ 0x80000000u);
}
__device__ __forceinline__ float decode_ord(unsigned u) {
    unsigned b = (u & 0x80000000u) ? (u ^ 0x80000000u) : ~u;
    return __uint_as_float(b);
}

// ---- K0: init scratch ----
__global__ void k_init(int n) {
    int t = threadIdx.x;
    if (t < BATCHES * INC) {
        g_segsum[t] = 0.f;
        g_segmax[t] = encode_ord(-INFINITY);
    }
    if (t < BATCHES) g_count[t] = 0.f;
    if (t == 0) g_sm[n] = make_float2(0.f, 0.f);  // pad row for missing neighbors
}

// ---- K1: segment sum/max of F with shared-memory staging ----
// 148 blocks x 512 threads (16 quads x 32 row-lanes). Register accum per thread,
// shared-atomic flush on (rare) batch change, single global-atomic flush per block.
__global__ __launch_bounds__(512) void k_seg(const float* __restrict__ F,
                                             const int* __restrict__ bidx, int n) {
    __shared__ float    s_sum[BATCHES * INC];
    __shared__ unsigned s_max[BATCHES * INC];
    __shared__ float    s_cnt[BATCHES];

    int t = threadIdx.x;
    for (int i = t; i < BATCHES * INC; i += 512) {
        s_sum[i] = 0.f;
        s_max[i] = encode_ord(-INFINITY);
    }
    if (t < BATCHES) s_cnt[t] = 0.f;
    __syncthreads();

    int chunk = (n + gridDim.x - 1) / gridDim.x;
    int start = blockIdx.x * chunk;
    int end   = min(start + chunk, n);

    int q     = t & 15;    // channel quad
    int rlane = t >> 4;    // 0..31

    float4 sum = make_float4(0.f, 0.f, 0.f, 0.f);
    float4 mx  = make_float4(-INFINITY, -INFINITY, -INFINITY, -INFINITY);
    float cnt = 0.f;
    int cur = -1;

    for (int r = start + rlane; r < end; r += 32) {
        int b = bidx[r];
        if (b != cur) {
            if (cur >= 0) {
                float*    ss = &s_sum[cur * INC + q * 4];
                unsigned* sx = &s_max[cur * INC + q * 4];
                atomicAdd(ss + 0, sum.x); atomicAdd(ss + 1, sum.y);
                atomicAdd(ss + 2, sum.z); atomicAdd(ss + 3, sum.w);
                atomicMax(sx + 0, encode_ord(mx.x)); atomicMax(sx + 1, encode_ord(mx.y));
                atomicMax(sx + 2, encode_ord(mx.z)); atomicMax(sx + 3, encode_ord(mx.w));
                if (q == 0) atomicAdd(&s_cnt[cur], cnt);
            }
            cur = b;
            sum = make_float4(0.f, 0.f, 0.f, 0.f);
            mx  = make_float4(-INFINITY, -INFINITY, -INFINITY, -INFINITY);
            cnt = 0.f;
        }
        float4 v = ((const float4*)(F + (long)r * INC))[q];
        sum.x += v.x; sum.y += v.y; sum.z += v.z; sum.w += v.w;
        mx.x = fmaxf(mx.x, v.x); mx.y = fmaxf(mx.y, v.y);
        mx.z = fmaxf(mx.z, v.z); mx.w = fmaxf(mx.w, v.w);
        cnt += 1.f;
    }
    if (cur >= 0) {
        float*    ss = &s_sum[cur * INC + q * 4];
        unsigned* sx = &s_max[cur * INC + q * 4];
        atomicAdd(ss + 0, sum.x); atomicAdd(ss + 1, sum.y);
        atomicAdd(ss + 2, sum.z); atomicAdd(ss + 3, sum.w);
        atomicMax(sx + 0, encode_ord(mx.x)); atomicMax(sx + 1, encode_ord(mx.y));
        atomicMax(sx + 2, encode_ord(mx.z)); atomicMax(sx + 3, encode_ord(mx.w));
        if (q == 0) atomicAdd(&s_cnt[cur], cnt);
    }
    __syncthreads();

    // global flush: only batches this block actually touched
    for (int i = t; i < BATCHES * INC; i += 512) {
        int b = i >> 6;
        if (s_cnt[b] > 0.f) {
            atomicAdd(&g_segsum[i], s_sum[i]);
            atomicMax(&g_segmax[i], s_max[i]);
        }
    }
    if (t < BATCHES && s_cnt[t] > 0.f) atomicAdd(&g_count[t], s_cnt[t]);
}

// ---- K2: tiny shared MLP -> per-batch channel gate (1 block) ----
__global__ void k_gate(const float* __restrict__ W1, const float* __restrict__ b1,
                       const float* __restrict__ W2, const float* __restrict__ b2) {
    __shared__ float h1a[BATCHES][HID], h1m[BATCHES][HID];
    int t = threadIdx.x;  // 128 threads
    if (t < BATCHES * HID) {
        int b = t / HID, j = t % HID;
        float sa = b1[j], sm = b1[j];
        float inv = 1.f / g_count[b];
        for (int c = 0; c < INC; c++) {
            float w    = W1[c * HID + j];
            float mean = g_segsum[b * INC + c] * inv;
            float mxv  = decode_ord(g_segmax[b * INC + c]);
            sa += mean * w;
            sm += mxv * w;
        }
        h1a[b][j] = fmaxf(sa, 0.f);
        h1m[b][j] = fmaxf(sm, 0.f);
    }
    __syncthreads();
    for (int t2 = t; t2 < BATCHES * INC; t2 += 128) {
        int b = t2 / INC, c = t2 % INC;
        float s = 2.f * b2[c];
        for (int j = 0; j < HID; j++)
            s += (h1a[b][j] + h1m[b][j]) * W2[j * INC + c];
        g_gate[t2] = 1.f / (1.f + expf(-s));
    }
}

// ---- K3: thread-per-row: z = F*gate ; sm = (mean_c z, max_c z). No shuffles. ----
__global__ void k_sm(const float* __restrict__ F, const int* __restrict__ bidx, int n) {
    int r = blockIdx.x * blockDim.x + threadIdx.x;
    if (r >= n) return;
    int b = bidx[r];
    const float4* fr = (const float4*)(F + (long)r * INC);
    const float4* gr = (const float4*)(g_gate + b * INC);
    float s = 0.f, m = -INFINITY;
    #pragma unroll
    for (int k = 0; k < 16; k++) {
        float4 f = fr[k];
        float4 g = gr[k];
        float z0 = f.x * g.x, z1 = f.y * g.y, z2 = f.z * g.z, z3 = f.w * g.w;
        s += (z0 + z1) + (z2 + z3);
        m = fmaxf(m, fmaxf(fmaxf(z0, z1), fmaxf(z2, z3)));
    }
    g_sm[r] = make_float2(s * (1.f / 64.f), m);
}

// ---- K4: thread-per-point 27-gather conv -> sigmoid. nbr staged via shared. ----
__global__ __launch_bounds__(256) void k_conv(const int* __restrict__ nbr,
                                              const float* __restrict__ conv_w, int n) {
    __shared__ float sw[54];
    __shared__ int s_nbr[256 * 27];
    int t = threadIdx.x;
    if (t < 54) sw[t] = conv_w[t];

    int base = blockIdx.x * 256;
    int cnt  = min(256, n - base);
    long off = (long)base * 27;
    for (int i = t; i < cnt * 27; i += 256) s_nbr[i] = nbr[off + i];
    __syncthreads();

    if (t < cnt) {
        const int* nb = &s_nbr[t * 27];
        float p = 0.f;
        #pragma unroll
        for (int k = 0; k < 27; k++) {
            float2 s = g_sm[nb[k]];           // L2-resident gather (2.4 MB)
            p += s.x * sw[2 * k] + s.y * sw[2 * k + 1];
        }
        g_sig[base + t] = 1.f / (1.f + expf(-p));
    }
}

// ---- K5: pure float4 stream: out = F * gate[bidx] * sig ----
__global__ void k_mul(const float* __restrict__ F, const int* __restrict__ bidx,
                      float* __restrict__ out, int n) {
    long total = (long)n * (INC / 4);
    long i = (long)blockIdx.x * blockDim.x + threadIdx.x;
    if (i >= total) return;
    int r  = (int)(i >> 4);
    int c4 = (int)(i & 15);
    float4 f = __ldcs((const float4*)F + i);
    int b = bidx[r];
    float4 g = ((const float4*)g_gate)[b * 16 + c4];
    float sg = g_sig[r];
    float4 o;
    o.x = f.x * g.x * sg; o.y = f.y * g.y * sg;
    o.z = f.z * g.z * sg; o.w = f.w * g.w * sg;
    __stcs((float4*)out + i, o);
}

extern "C" void kernel_launch(void* const* d_in, const int* in_sizes, int n_in,
                              void* d_out, int out_size) {
    const float* F      = (const float*)d_in[0];
    const int*   bidx   = (const int*)d_in[1];
    const int*   nbr    = (const int*)d_in[2];
    const float* W1     = (const float*)d_in[3];
    const float* b1     = (const float*)d_in[4];
    const float* W2     = (const float*)d_in[5];
    const float* b2     = (const float*)d_in[6];
    const float* conv_w = (const float*)d_in[7];
    float* out = (float*)d_out;
    int n = in_sizes[1];   // batch_idx length = N

    k_init<<<1, 512>>>(n);
    k_seg<<<148, 512>>>(F, bidx, n);
    k_gate<<<1, 128>>>(W1, b1, W2, b2);
    k_sm<<<(n + 255) / 256, 256>>>(F, bidx, n);
    k_conv<<<(n + 255) / 256, 256>>>(nbr, conv_w, n);

    long total4 = (long)n * (INC / 4);
    k_mul<<<(int)((total4 + 255) / 256), 256>>>(F, bidx, out, n);
}

// round 4
// speedup vs baseline: 2.0764x; 1.7720x over previous
#include <cuda_runtime.h>
#include <math.h>

#define INC 64
#define HID 16
#define BATCHES 8
#define NMAX 300032   // N=300000 (+ pad row)

// ---- scratch (no allocations allowed) ----
__device__ float    g_segsum[BATCHES * INC];
__device__ unsigned g_segmax[BATCHES * INC];   // order-encoded float
__device__ float    g_count[BATCHES];
__device__ float    g_gate[BATCHES * INC];
__device__ float2   g_sm[NMAX];                // (mean, max) per point, + zero pad row
__device__ float    g_sig[NMAX];               // spatial sigmoid per point

__device__ __forceinline__ unsigned encode_ord(float f) {
    unsigned b = __float_as_uint(f);
    return (b & 0x80000000u) ? ~b : (b ^ 0x80000000u);
}
__device__ __forceinline__ float decode_ord(unsigned u) {
    unsigned b = (u & 0x80000000u) ? (u ^ 0x80000000u) : ~u;
    return __uint_as_float(b);
}

// ---- K0: init scratch ----
__global__ void k_init(int n) {
    int t = threadIdx.x;
    if (t < BATCHES * INC) {
        g_segsum[t] = 0.f;
        g_segmax[t] = encode_ord(-INFINITY);
    }
    if (t < BATCHES) g_count[t] = 0.f;
    if (t == 0) g_sm[n] = make_float2(0.f, 0.f);  // pad row for missing neighbors
}

// ---- K1: segment sum/max of F with shared-memory staging ----
__global__ __launch_bounds__(512) void k_seg(const float* __restrict__ F,
                                             const int* __restrict__ bidx, int n) {
    __shared__ float    s_sum[BATCHES * INC];
    __shared__ unsigned s_max[BATCHES * INC];
    __shared__ float    s_cnt[BATCHES];

    int t = threadIdx.x;
    for (int i = t; i < BATCHES * INC; i += 512) {
        s_sum[i] = 0.f;
        s_max[i] = encode_ord(-INFINITY);
    }
    if (t < BATCHES) s_cnt[t] = 0.f;
    __syncthreads();

    int chunk = (n + gridDim.x - 1) / gridDim.x;
    int start = blockIdx.x * chunk;
    int end   = min(start + chunk, n);

    int q     = t & 15;    // channel quad
    int rlane = t >> 4;    // 0..31

    float4 sum = make_float4(0.f, 0.f, 0.f, 0.f);
    float4 mx  = make_float4(-INFINITY, -INFINITY, -INFINITY, -INFINITY);
    float cnt = 0.f;
    int cur = -1;

    for (int r = start + rlane; r < end; r += 32) {
        int b = bidx[r];
        if (b != cur) {
            if (cur >= 0) {
                float*    ss = &s_sum[cur * INC + q * 4];
                unsigned* sx = &s_max[cur * INC + q * 4];
                atomicAdd(ss + 0, sum.x); atomicAdd(ss + 1, sum.y);
                atomicAdd(ss + 2, sum.z); atomicAdd(ss + 3, sum.w);
                atomicMax(sx + 0, encode_ord(mx.x)); atomicMax(sx + 1, encode_ord(mx.y));
                atomicMax(sx + 2, encode_ord(mx.z)); atomicMax(sx + 3, encode_ord(mx.w));
                if (q == 0) atomicAdd(&s_cnt[cur], cnt);
            }
            cur = b;
            sum = make_float4(0.f, 0.f, 0.f, 0.f);
            mx  = make_float4(-INFINITY, -INFINITY, -INFINITY, -INFINITY);
            cnt = 0.f;
        }
        float4 v = ((const float4*)(F + (long)r * INC))[q];
        sum.x += v.x; sum.y += v.y; sum.z += v.z; sum.w += v.w;
        mx.x = fmaxf(mx.x, v.x); mx.y = fmaxf(mx.y, v.y);
        mx.z = fmaxf(mx.z, v.z); mx.w = fmaxf(mx.w, v.w);
        cnt += 1.f;
    }
    if (cur >= 0) {
        float*    ss = &s_sum[cur * INC + q * 4];
        unsigned* sx = &s_max[cur * INC + q * 4];
        atomicAdd(ss + 0, sum.x); atomicAdd(ss + 1, sum.y);
        atomicAdd(ss + 2, sum.z); atomicAdd(ss + 3, sum.w);
        atomicMax(sx + 0, encode_ord(mx.x)); atomicMax(sx + 1, encode_ord(mx.y));
        atomicMax(sx + 2, encode_ord(mx.z)); atomicMax(sx + 3, encode_ord(mx.w));
        if (q == 0) atomicAdd(&s_cnt[cur], cnt);
    }
    __syncthreads();

    for (int i = t; i < BATCHES * INC; i += 512) {
        int b = i >> 6;
        if (s_cnt[b] > 0.f) {
            atomicAdd(&g_segsum[i], s_sum[i]);
            atomicMax(&g_segmax[i], s_max[i]);
        }
    }
    if (t < BATCHES && s_cnt[t] > 0.f) atomicAdd(&g_count[t], s_cnt[t]);
}

// ---- K2: tiny shared MLP -> per-batch channel gate (1 block) ----
__global__ void k_gate(const float* __restrict__ W1, const float* __restrict__ b1,
                       const float* __restrict__ W2, const float* __restrict__ b2) {
    __shared__ float h1a[BATCHES][HID], h1m[BATCHES][HID];
    int t = threadIdx.x;  // 128 threads
    if (t < BATCHES * HID) {
        int b = t / HID, j = t % HID;
        float sa = b1[j], sm = b1[j];
        float inv = 1.f / g_count[b];
        for (int c = 0; c < INC; c++) {
            float w    = W1[c * HID + j];
            float mean = g_segsum[b * INC + c] * inv;
            float mxv  = decode_ord(g_segmax[b * INC + c]);
            sa += mean * w;
            sm += mxv * w;
        }
        h1a[b][j] = fmaxf(sa, 0.f);
        h1m[b][j] = fmaxf(sm, 0.f);
    }
    __syncthreads();
    for (int t2 = t; t2 < BATCHES * INC; t2 += 128) {
        int b = t2 / INC, c = t2 % INC;
        float s = 2.f * b2[c];
        for (int j = 0; j < HID; j++)
            s += (h1a[b][j] + h1m[b][j]) * W2[j * INC + c];
        g_gate[t2] = 1.f / (1.f + expf(-s));
    }
}

// ---- K3: half-warp-per-row, float4, 2-row unroll for shuffle-latency hiding ----
__global__ __launch_bounds__(256) void k_sm(const float* __restrict__ F,
                                            const int* __restrict__ bidx, int n) {
    int gtid   = blockIdx.x * blockDim.x + threadIdx.x;
    int hw     = gtid >> 4;             // half-warp id
    int lane16 = threadIdx.x & 15;
    int nhw    = (gridDim.x * blockDim.x) >> 4;

    int r0 = hw * 2;
    int stride = nhw * 2;
    for (; r0 + 1 < n; r0 += stride) {
        int r1 = r0 + 1;
        int b0 = bidx[r0], b1 = bidx[r1];
        float4 fA = ((const float4*)(F + (long)r0 * INC))[lane16];
        float4 fB = ((const float4*)(F + (long)r1 * INC))[lane16];
        float4 gA = ((const float4*)(g_gate + b0 * INC))[lane16];
        float4 gB = ((const float4*)(g_gate + b1 * INC))[lane16];
        float a0 = fA.x * gA.x, a1 = fA.y * gA.y, a2 = fA.z * gA.z, a3 = fA.w * gA.w;
        float c0 = fB.x * gB.x, c1 = fB.y * gB.y, c2 = fB.z * gB.z, c3 = fB.w * gB.w;
        float sA = (a0 + a1) + (a2 + a3);
        float mA = fmaxf(fmaxf(a0, a1), fmaxf(a2, a3));
        float sB = (c0 + c1) + (c2 + c3);
        float mB = fmaxf(fmaxf(c0, c1), fmaxf(c2, c3));
        #pragma unroll
        for (int o = 8; o > 0; o >>= 1) {
            sA += __shfl_xor_sync(0xffffffffu, sA, o);
            sB += __shfl_xor_sync(0xffffffffu, sB, o);
            mA = fmaxf(mA, __shfl_xor_sync(0xffffffffu, mA, o));
            mB = fmaxf(mB, __shfl_xor_sync(0xffffffffu, mB, o));
        }
        if (lane16 == 0) {
            g_sm[r0] = make_float2(sA * (1.f / 64.f), mA);
            g_sm[r1] = make_float2(sB * (1.f / 64.f), mB);
        }
    }
    // tail (at most 1 row, only the first half-warp that lands on it)
    if (r0 < n) {
        int b = bidx[r0];
        float4 f = ((const float4*)(F + (long)r0 * INC))[lane16];
        float4 g = ((const float4*)(g_gate + b * INC))[lane16];
        float z0 = f.x * g.x, z1 = f.y * g.y, z2 = f.z * g.z, z3 = f.w * g.w;
        float s = (z0 + z1) + (z2 + z3);
        float m = fmaxf(fmaxf(z0, z1), fmaxf(z2, z3));
        #pragma unroll
        for (int o = 8; o > 0; o >>= 1) {
            s += __shfl_xor_sync(0xffffffffu, s, o);
            m = fmaxf(m, __shfl_xor_sync(0xffffffffu, m, o));
        }
        if (lane16 == 0) g_sm[r0] = make_float2(s * (1.f / 64.f), m);
    }
}

// ---- K4: thread-per-point 27-gather conv -> sigmoid. nbr staged via shared. ----
__global__ __launch_bounds__(256) void k_conv(const int* __restrict__ nbr,
                                              const float* __restrict__ conv_w, int n) {
    __shared__ float sw[54];
    __shared__ int s_nbr[256 * 27];
    int t = threadIdx.x;
    if (t < 54) sw[t] = conv_w[t];

    int base = blockIdx.x * 256;
    int cnt  = min(256, n - base);
    long off = (long)base * 27;
    for (int i = t; i < cnt * 27; i += 256) s_nbr[i] = nbr[off + i];
    __syncthreads();

    if (t < cnt) {
        const int* nb = &s_nbr[t * 27];
        float p = 0.f;
        #pragma unroll
        for (int k = 0; k < 27; k++) {
            float2 s = g_sm[nb[k]];           // L2-resident gather (2.4 MB)
            p += s.x * sw[2 * k] + s.y * sw[2 * k + 1];
        }
        g_sig[base + t] = 1.f / (1.f + expf(-p));
    }
}

// ---- K5: pure float4 stream: out = F * gate[bidx] * sig ----
__global__ void k_mul(const float* __restrict__ F, const int* __restrict__ bidx,
                      float* __restrict__ out, int n) {
    long total = (long)n * (INC / 4);
    long i = (long)blockIdx.x * blockDim.x + threadIdx.x;
    if (i >= total) return;
    int r  = (int)(i >> 4);
    int c4 = (int)(i & 15);
    float4 f = ((const float4*)F)[i];          // default policy: hit L2 from k_sm pass
    int b = bidx[r];
    float4 g = ((const float4*)g_gate)[b * 16 + c4];
    float sg = g_sig[r];
    float4 o;
    o.x = f.x * g.x * sg; o.y = f.y * g.y * sg;
    o.z = f.z * g.z * sg; o.w = f.w * g.w * sg;
    __stcs((float4*)out + i, o);
}

extern "C" void kernel_launch(void* const* d_in, const int* in_sizes, int n_in,
                              void* d_out, int out_size) {
    const float* F      = (const float*)d_in[0];
    const int*   bidx   = (const int*)d_in[1];
    const int*   nbr    = (const int*)d_in[2];
    const float* W1     = (const float*)d_in[3];
    const float* b1     = (const float*)d_in[4];
    const float* W2     = (const float*)d_in[5];
    const float* b2     = (const float*)d_in[6];
    const float* conv_w = (const float*)d_in[7];
    float* out = (float*)d_out;
    int n = in_sizes[1];   // batch_idx length = N

    k_init<<<1, 512>>>(n);
    k_seg<<<444, 512>>>(F, bidx, n);
    k_gate<<<1, 128>>>(W1, b1, W2, b2);
    k_sm<<<1184, 256>>>(F, bidx, n);
    k_conv<<<(n + 255) / 256, 256>>>(nbr, conv_w, n);

    long total4 = (long)n * (INC / 4);
    k_mul<<<(int)((total4 + 255) / 256), 256>>>(F, bidx, out, n);
}

// round 5
// speedup vs baseline: 2.1648x; 1.0426x over previous
#include <cuda_runtime.h>
#include <math.h>

#define INC 64
#define HID 16
#define BATCHES 8
#define NMAX 300032   // N=300000 (+ pad row)

// ---- scratch (zero-initialized at module load; k_gate re-zeros after use) ----
__device__ float    g_segsum[BATCHES * INC];
__device__ unsigned g_segmax[BATCHES * INC];   // order-encoded float; 0 == identity (< any real)
__device__ float    g_count[BATCHES];
__device__ float    g_gate[BATCHES * INC];
__device__ float2   g_sm[NMAX];                // (mean, max) per point, + zero pad row

__device__ __forceinline__ unsigned encode_ord(float f) {
    unsigned b = __float_as_uint(f);
    return (b & 0x80000000u) ? ~b : (b ^ 0x80000000u);
}
__device__ __forceinline__ float decode_ord(unsigned u) {
    unsigned b = (u & 0x80000000u) ? (u ^ 0x80000000u) : ~u;
    return __uint_as_float(b);
}

// ---- K1: segment sum/max of F with shared-memory staging ----
__global__ __launch_bounds__(512) void k_seg(const float* __restrict__ F,
                                             const int* __restrict__ bidx, int n) {
    __shared__ float    s_sum[BATCHES * INC];
    __shared__ unsigned s_max[BATCHES * INC];
    __shared__ float    s_cnt[BATCHES];

    int t = threadIdx.x;
    for (int i = t; i < BATCHES * INC; i += 512) {
        s_sum[i] = 0.f;
        s_max[i] = 0u;                 // encoded identity (< any real value)
    }
    if (t < BATCHES) s_cnt[t] = 0.f;
    __syncthreads();

    int chunk = (n + gridDim.x - 1) / gridDim.x;
    int start = blockIdx.x * chunk;
    int end   = min(start + chunk, n);

    int q     = t & 15;    // channel quad
    int rlane = t >> 4;    // 0..31

    float4 sum = make_float4(0.f, 0.f, 0.f, 0.f);
    float4 mx  = make_float4(-INFINITY, -INFINITY, -INFINITY, -INFINITY);
    float cnt = 0.f;
    int cur = -1;

    for (int r = start + rlane; r < end; r += 32) {
        int b = bidx[r];
        if (b != cur) {
            if (cur >= 0) {
                float*    ss = &s_sum[cur * INC + q * 4];
                unsigned* sx = &s_max[cur * INC + q * 4];
                atomicAdd(ss + 0, sum.x); atomicAdd(ss + 1, sum.y);
                atomicAdd(ss + 2, sum.z); atomicAdd(ss + 3, sum.w);
                atomicMax(sx + 0, encode_ord(mx.x)); atomicMax(sx + 1, encode_ord(mx.y));
                atomicMax(sx + 2, encode_ord(mx.z)); atomicMax(sx + 3, encode_ord(mx.w));
                if (q == 0) atomicAdd(&s_cnt[cur], cnt);
            }
            cur = b;
            sum = make_float4(0.f, 0.f, 0.f, 0.f);
            mx  = make_float4(-INFINITY, -INFINITY, -INFINITY, -INFINITY);
            cnt = 0.f;
        }
        float4 v = ((const float4*)(F + (long)r * INC))[q];
        sum.x += v.x; sum.y += v.y; sum.z += v.z; sum.w += v.w;
        mx.x = fmaxf(mx.x, v.x); mx.y = fmaxf(mx.y, v.y);
        mx.z = fmaxf(mx.z, v.z); mx.w = fmaxf(mx.w, v.w);
        cnt += 1.f;
    }
    if (cur >= 0) {
        float*    ss = &s_sum[cur * INC + q * 4];
        unsigned* sx = &s_max[cur * INC + q * 4];
        atomicAdd(ss + 0, sum.x); atomicAdd(ss + 1, sum.y);
        atomicAdd(ss + 2, sum.z); atomicAdd(ss + 3, sum.w);
        atomicMax(sx + 0, encode_ord(mx.x)); atomicMax(sx + 1, encode_ord(mx.y));
        atomicMax(sx + 2, encode_ord(mx.z)); atomicMax(sx + 3, encode_ord(mx.w));
        if (q == 0) atomicAdd(&s_cnt[cur], cnt);
    }
    __syncthreads();

    for (int i = t; i < BATCHES * INC; i += 512) {
        int b = i >> 6;
        if (s_cnt[b] > 0.f) {
            atomicAdd(&g_segsum[i], s_sum[i]);
            atomicMax(&g_segmax[i], s_max[i]);
        }
    }
    if (t < BATCHES && s_cnt[t] > 0.f) atomicAdd(&g_count[t], s_cnt[t]);
}

// ---- K2: tiny shared MLP -> per-batch gate; then RESET accumulators for next call ----
__global__ void k_gate(const float* __restrict__ W1, const float* __restrict__ b1,
                       const float* __restrict__ W2, const float* __restrict__ b2) {
    __shared__ float h1a[BATCHES][HID], h1m[BATCHES][HID];
    int t = threadIdx.x;  // 128 threads
    if (t < BATCHES * HID) {
        int b = t / HID, j = t % HID;
        float sa = b1[j], sm = b1[j];
        float inv = 1.f / g_count[b];
        for (int c = 0; c < INC; c++) {
            float w    = W1[c * HID + j];
            float mean = g_segsum[b * INC + c] * inv;
            float mxv  = decode_ord(g_segmax[b * INC + c]);
            sa += mean * w;
            sm += mxv * w;
        }
        h1a[b][j] = fmaxf(sa, 0.f);
        h1m[b][j] = fmaxf(sm, 0.f);
    }
    __syncthreads();
    // reset accumulators (all reads of them are done) — keeps each call deterministic
    for (int i = t; i < BATCHES * INC; i += 128) {
        g_segsum[i] = 0.f;
        g_segmax[i] = 0u;
    }
    if (t < BATCHES) g_count[t] = 0.f;

    for (int t2 = t; t2 < BATCHES * INC; t2 += 128) {
        int b = t2 / INC, c = t2 % INC;
        float s = 2.f * b2[c];
        for (int j = 0; j < HID; j++)
            s += (h1a[b][j] + h1m[b][j]) * W2[j * INC + c];
        g_gate[t2] = 1.f / (1.f + expf(-s));
    }
}

// ---- K3: half-warp-per-row, float4, 2-row unroll for shuffle-latency hiding ----
__global__ __launch_bounds__(256) void k_sm(const float* __restrict__ F,
                                            const int* __restrict__ bidx, int n) {
    int gtid   = blockIdx.x * blockDim.x + threadIdx.x;
    if (gtid == 0) g_sm[n] = make_float2(0.f, 0.f);   // pad row for missing neighbors
    int hw     = gtid >> 4;             // half-warp id
    int lane16 = threadIdx.x & 15;
    int nhw    = (gridDim.x * blockDim.x) >> 4;

    int r0 = hw * 2;
    int stride = nhw * 2;
    for (; r0 + 1 < n; r0 += stride) {
        int r1 = r0 + 1;
        int b0 = bidx[r0], b1 = bidx[r1];
        float4 fA = ((const float4*)(F + (long)r0 * INC))[lane16];
        float4 fB = ((const float4*)(F + (long)r1 * INC))[lane16];
        float4 gA = ((const float4*)(g_gate + b0 * INC))[lane16];
        float4 gB = ((const float4*)(g_gate + b1 * INC))[lane16];
        float a0 = fA.x * gA.x, a1 = fA.y * gA.y, a2 = fA.z * gA.z, a3 = fA.w * gA.w;
        float c0 = fB.x * gB.x, c1 = fB.y * gB.y, c2 = fB.z * gB.z, c3 = fB.w * gB.w;
        float sA = (a0 + a1) + (a2 + a3);
        float mA = fmaxf(fmaxf(a0, a1), fmaxf(a2, a3));
        float sB = (c0 + c1) + (c2 + c3);
        float mB = fmaxf(fmaxf(c0, c1), fmaxf(c2, c3));
        #pragma unroll
        for (int o = 8; o > 0; o >>= 1) {
            sA += __shfl_xor_sync(0xffffffffu, sA, o);
            sB += __shfl_xor_sync(0xffffffffu, sB, o);
            mA = fmaxf(mA, __shfl_xor_sync(0xffffffffu, mA, o));
            mB = fmaxf(mB, __shfl_xor_sync(0xffffffffu, mB, o));
        }
        if (lane16 == 0) {
            g_sm[r0] = make_float2(sA * (1.f / 64.f), mA);
            g_sm[r1] = make_float2(sB * (1.f / 64.f), mB);
        }
    }
    if (r0 < n) {   // tail (at most 1 row)
        int b = bidx[r0];
        float4 f = ((const float4*)(F + (long)r0 * INC))[lane16];
        float4 g = ((const float4*)(g_gate + b * INC))[lane16];
        float z0 = f.x * g.x, z1 = f.y * g.y, z2 = f.z * g.z, z3 = f.w * g.w;
        float s = (z0 + z1) + (z2 + z3);
        float m = fmaxf(fmaxf(z0, z1), fmaxf(z2, z3));
        #pragma unroll
        for (int o = 8; o > 0; o >>= 1) {
            s += __shfl_xor_sync(0xffffffffu, s, o);
            m = fmaxf(m, __shfl_xor_sync(0xffffffffu, m, o));
        }
        if (lane16 == 0) g_sm[r0] = make_float2(s * (1.f / 64.f), m);
    }
}

// ---- K4: fused conv + output stream. Block handles 256 points:
//      phase 1: per-thread 27-gather conv -> sig in smem
//      phase 2: coalesced float4 stream out = F * gate * sig ----
__global__ __launch_bounds__(256) void k_convmul(const float* __restrict__ F,
                                                 const int* __restrict__ bidx,
                                                 const int* __restrict__ nbr,
                                                 const float* __restrict__ conv_w,
                                                 float* __restrict__ out, int n) {
    __shared__ float sw[54];
    __shared__ int   s_nbr[256 * 27];
    __shared__ float s_sig[256];
    __shared__ int   s_b[256];

    int t = threadIdx.x;
    if (t < 54) sw[t] = conv_w[t];

    int base = blockIdx.x * 256;
    int cnt  = min(256, n - base);
    long off = (long)base * 27;
    for (int i = t; i < cnt * 27; i += 256) s_nbr[i] = nbr[off + i];
    if (t < cnt) s_b[t] = bidx[base + t];
    __syncthreads();

    if (t < cnt) {
        const int* nb = &s_nbr[t * 27];
        float p = 0.f;
        #pragma unroll
        for (int k = 0; k < 27; k++) {
            float2 s = g_sm[nb[k]];           // L2-resident gather (2.4 MB)
            p += s.x * sw[2 * k] + s.y * sw[2 * k + 1];
        }
        s_sig[t] = 1.f / (1.f + expf(-p));
    }
    __syncthreads();

    // phase 2: cnt rows * 16 float4 each, fully coalesced across the block
    long fbase = (long)base * 16;             // float4 offset of tile start
    int total4 = cnt * 16;
    for (int il = t; il < total4; il += 256) {
        int rl = il >> 4;                     // local row
        int c4 = il & 15;
        float4 f = ((const float4*)F)[fbase + il];
        float4 g = ((const float4*)g_gate)[s_b[rl] * 16 + c4];
        float sg = s_sig[rl];
        float4 o;
        o.x = f.x * g.x * sg; o.y = f.y * g.y * sg;
        o.z = f.z * g.z * sg; o.w = f.w * g.w * sg;
        __stcs((float4*)out + fbase + il, o);
    }
}

extern "C" void kernel_launch(void* const* d_in, const int* in_sizes, int n_in,
                              void* d_out, int out_size) {
    const float* F      = (const float*)d_in[0];
    const int*   bidx   = (const int*)d_in[1];
    const int*   nbr    = (const int*)d_in[2];
    const float* W1     = (const float*)d_in[3];
    const float* b1     = (const float*)d_in[4];
    const float* W2     = (const float*)d_in[5];
    const float* b2     = (const float*)d_in[6];
    const float* conv_w = (const float*)d_in[7];
    float* out = (float*)d_out;
    int n = in_sizes[1];   // batch_idx length = N

    k_seg<<<444, 512>>>(F, bidx, n);
    k_gate<<<1, 128>>>(W1, b1, W2, b2);
    k_sm<<<1184, 256>>>(F, bidx, n);
    k_convmul<<<(n + 255) / 256, 256>>>(F, bidx, nbr, conv_w, out, n);
}

// round 6
// speedup vs baseline: 2.2140x; 1.0227x over previous
#include <cuda_runtime.h>
#include <math.h>

#define INC 64
#define HID 16
#define BATCHES 8
#define NMAX 300032   // N=300000 (+ pad row)

// ---- scratch (zero-initialized at module load; k_gate re-zeros after use) ----
__device__ float    g_segsum[BATCHES * INC];
__device__ unsigned g_segmax[BATCHES * INC];   // order-encoded float; 0 == identity
__device__ float    g_count[BATCHES];
__device__ float    g_gate[BATCHES * INC];
__device__ float2   g_sm[NMAX];                // (mean, max) per point, + zero pad row
__device__ float    g_sig[NMAX];               // spatial sigmoid per point

__device__ __forceinline__ unsigned encode_ord(float f) {
    unsigned b = __float_as_uint(f);
    return (b & 0x80000000u) ? ~b : (b ^ 0x80000000u);
}
__device__ __forceinline__ float decode_ord(unsigned u) {
    unsigned b = (u & 0x80000000u) ? (u ^ 0x80000000u) : ~u;
    return __uint_as_float(b);
}

__device__ __forceinline__ void accum4(float4& sum, float4& mx, float4 v) {
    sum.x += v.x; sum.y += v.y; sum.z += v.z; sum.w += v.w;
    mx.x = fmaxf(mx.x, v.x); mx.y = fmaxf(mx.y, v.y);
    mx.z = fmaxf(mx.z, v.z); mx.w = fmaxf(mx.w, v.w);
}

__device__ __forceinline__ void flush_seg(float* s_sum, unsigned* s_max, float* s_cnt,
                                          int cur, int q, float4& sum, float4& mx,
                                          float& cnt) {
    float*    ss = &s_sum[cur * INC + q * 4];
    unsigned* sx = &s_max[cur * INC + q * 4];
    atomicAdd(ss + 0, sum.x); atomicAdd(ss + 1, sum.y);
    atomicAdd(ss + 2, sum.z); atomicAdd(ss + 3, sum.w);
    atomicMax(sx + 0, encode_ord(mx.x)); atomicMax(sx + 1, encode_ord(mx.y));
    atomicMax(sx + 2, encode_ord(mx.z)); atomicMax(sx + 3, encode_ord(mx.w));
    if (q == 0) atomicAdd(&s_cnt[cur], cnt);
    sum = make_float4(0.f, 0.f, 0.f, 0.f);
    mx  = make_float4(-INFINITY, -INFINITY, -INFINITY, -INFINITY);
    cnt = 0.f;
}

// ---- K1: segment sum/max, shared staging, 2-row ILP per thread ----
__global__ __launch_bounds__(512) void k_seg(const float* __restrict__ F,
                                             const int* __restrict__ bidx, int n) {
    __shared__ float    s_sum[BATCHES * INC];
    __shared__ unsigned s_max[BATCHES * INC];
    __shared__ float    s_cnt[BATCHES];

    int t = threadIdx.x;
    for (int i = t; i < BATCHES * INC; i += 512) { s_sum[i] = 0.f; s_max[i] = 0u; }
    if (t < BATCHES) s_cnt[t] = 0.f;
    __syncthreads();

    int chunk = (n + gridDim.x - 1) / gridDim.x;
    int start = blockIdx.x * chunk;
    int end   = min(start + chunk, n);

    int q     = t & 15;    // channel quad
    int rlane = t >> 4;    // 0..31

    float4 sum = make_float4(0.f, 0.f, 0.f, 0.f);
    float4 mx  = make_float4(-INFINITY, -INFINITY, -INFINITY, -INFINITY);
    float cnt = 0.f;
    int cur = -1;

    int r = start + rlane * 2;
    for (; r + 1 < end; r += 64) {
        int b0 = bidx[r], b1 = bidx[r + 1];
        float4 v0 = ((const float4*)(F + (long)r * INC))[q];
        float4 v1 = ((const float4*)(F + (long)(r + 1) * INC))[q];
        if (b0 != cur) {
            if (cur >= 0) flush_seg(s_sum, s_max, s_cnt, cur, q, sum, mx, cnt);
            cur = b0;
        }
        accum4(sum, mx, v0); cnt += 1.f;
        if (b1 != cur) {
            flush_seg(s_sum, s_max, s_cnt, cur, q, sum, mx, cnt);
            cur = b1;
        }
        accum4(sum, mx, v1); cnt += 1.f;
    }
    if (r < end) {
        int b0 = bidx[r];
        float4 v0 = ((const float4*)(F + (long)r * INC))[q];
        if (b0 != cur) {
            if (cur >= 0) flush_seg(s_sum, s_max, s_cnt, cur, q, sum, mx, cnt);
            cur = b0;
        }
        accum4(sum, mx, v0); cnt += 1.f;
    }
    if (cur >= 0) flush_seg(s_sum, s_max, s_cnt, cur, q, sum, mx, cnt);
    __syncthreads();

    for (int i = t; i < BATCHES * INC; i += 512) {
        int b = i >> 6;
        if (s_cnt[b] > 0.f) {
            atomicAdd(&g_segsum[i], s_sum[i]);
            atomicMax(&g_segmax[i], s_max[i]);
        }
    }
    if (t < BATCHES && s_cnt[t] > 0.f) atomicAdd(&g_count[t], s_cnt[t]);
}

// ---- K2: tiny shared MLP -> per-batch gate; then RESET accumulators ----
__global__ void k_gate(const float* __restrict__ W1, const float* __restrict__ b1,
                       const float* __restrict__ W2, const float* __restrict__ b2) {
    __shared__ float h1a[BATCHES][HID], h1m[BATCHES][HID];
    int t = threadIdx.x;  // 128 threads
    if (t < BATCHES * HID) {
        int b = t / HID, j = t % HID;
        float sa = b1[j], sm = b1[j];
        float inv = 1.f / g_count[b];
        for (int c = 0; c < INC; c++) {
            float w    = W1[c * HID + j];
            float mean = g_segsum[b * INC + c] * inv;
            float mxv  = decode_ord(g_segmax[b * INC + c]);
            sa += mean * w;
            sm += mxv * w;
        }
        h1a[b][j] = fmaxf(sa, 0.f);
        h1m[b][j] = fmaxf(sm, 0.f);
    }
    __syncthreads();
    for (int i = t; i < BATCHES * INC; i += 128) {   // reset for next call
        g_segsum[i] = 0.f;
        g_segmax[i] = 0u;
    }
    if (t < BATCHES) g_count[t] = 0.f;

    for (int t2 = t; t2 < BATCHES * INC; t2 += 128) {
        int b = t2 / INC, c = t2 % INC;
        float s = 2.f * b2[c];
        for (int j = 0; j < HID; j++)
            s += (h1a[b][j] + h1m[b][j]) * W2[j * INC + c];
        g_gate[t2] = 1.f / (1.f + expf(-s));
    }
}

// ---- K3: half-warp-per-row, float4, 2-row unroll ----
__global__ __launch_bounds__(256) void k_sm(const float* __restrict__ F,
                                            const int* __restrict__ bidx, int n) {
    int gtid   = blockIdx.x * blockDim.x + threadIdx.x;
    if (gtid == 0) g_sm[n] = make_float2(0.f, 0.f);   // pad row
    int hw     = gtid >> 4;
    int lane16 = threadIdx.x & 15;
    int nhw    = (gridDim.x * blockDim.x) >> 4;

    int r0 = hw * 2;
    int stride = nhw * 2;
    for (; r0 + 1 < n; r0 += stride) {
        int r1 = r0 + 1;
        int b0 = bidx[r0], b1 = bidx[r1];
        float4 fA = ((const float4*)(F + (long)r0 * INC))[lane16];
        float4 fB = ((const float4*)(F + (long)r1 * INC))[lane16];
        float4 gA = ((const float4*)(g_gate + b0 * INC))[lane16];
        float4 gB = ((const float4*)(g_gate + b1 * INC))[lane16];
        float a0 = fA.x * gA.x, a1 = fA.y * gA.y, a2 = fA.z * gA.z, a3 = fA.w * gA.w;
        float c0 = fB.x * gB.x, c1 = fB.y * gB.y, c2 = fB.z * gB.z, c3 = fB.w * gB.w;
        float sA = (a0 + a1) + (a2 + a3);
        float mA = fmaxf(fmaxf(a0, a1), fmaxf(a2, a3));
        float sB = (c0 + c1) + (c2 + c3);
        float mB = fmaxf(fmaxf(c0, c1), fmaxf(c2, c3));
        #pragma unroll
        for (int o = 8; o > 0; o >>= 1) {
            sA += __shfl_xor_sync(0xffffffffu, sA, o);
            sB += __shfl_xor_sync(0xffffffffu, sB, o);
            mA = fmaxf(mA, __shfl_xor_sync(0xffffffffu, mA, o));
            mB = fmaxf(mB, __shfl_xor_sync(0xffffffffu, mB, o));
        }
        if (lane16 == 0) {
            g_sm[r0] = make_float2(sA * (1.f / 64.f), mA);
            g_sm[r1] = make_float2(sB * (1.f / 64.f), mB);
        }
    }
    if (r0 < n) {   // tail
        int b = bidx[r0];
        float4 f = ((const float4*)(F + (long)r0 * INC))[lane16];
        float4 g = ((const float4*)(g_gate + b * INC))[lane16];
        float z0 = f.x * g.x, z1 = f.y * g.y, z2 = f.z * g.z, z3 = f.w * g.w;
        float s = (z0 + z1) + (z2 + z3);
        float m = fmaxf(fmaxf(z0, z1), fmaxf(z2, z3));
        #pragma unroll
        for (int o = 8; o > 0; o >>= 1) {
            s += __shfl_xor_sync(0xffffffffu, s, o);
            m = fmaxf(m, __shfl_xor_sync(0xffffffffu, m, o));
        }
        if (lane16 == 0) g_sm[r0] = make_float2(s * (1.f / 64.f), m);
    }
}

// ---- K4: thread-per-point 27-gather conv -> sigmoid. nbr staged via shared. ----
__global__ __launch_bounds__(256) void k_conv(const int* __restrict__ nbr,
                                              const float* __restrict__ conv_w, int n) {
    __shared__ float sw[54];
    __shared__ int s_nbr[256 * 27];
    int t = threadIdx.x;
    if (t < 54) sw[t] = conv_w[t];

    int base = blockIdx.x * 256;
    int cnt  = min(256, n - base);
    long off = (long)base * 27;
    for (int i = t; i < cnt * 27; i += 256) s_nbr[i] = nbr[off + i];
    __syncthreads();

    if (t < cnt) {
        const int* nb = &s_nbr[t * 27];
        float p = 0.f;
        #pragma unroll
        for (int k = 0; k < 27; k++) {
            float2 s = g_sm[nb[k]];           // L2-resident gather (2.4 MB)
            p += s.x * sw[2 * k] + s.y * sw[2 * k + 1];
        }
        g_sig[base + t] = 1.f / (1.f + expf(-p));
    }
}

// ---- K5: pure float4 stream: out = F * gate[bidx] * sig ----
__global__ void k_mul(const float* __restrict__ F, const int* __restrict__ bidx,
                      float* __restrict__ out, int n) {
    long total = (long)n * (INC / 4);
    long i = (long)blockIdx.x * blockDim.x + threadIdx.x;
    if (i >= total) return;
    int r  = (int)(i >> 4);
    int c4 = (int)(i & 15);
    float4 f = ((const float4*)F)[i];
    int b = bidx[r];
    float4 g = ((const float4*)g_gate)[b * 16 + c4];
    float sg = g_sig[r];
    float4 o;
    o.x = f.x * g.x * sg; o.y = f.y * g.y * sg;
    o.z = f.z * g.z * sg; o.w = f.w * g.w * sg;
    __stcs((float4*)out + i, o);
}

extern "C" void kernel_launch(void* const* d_in, const int* in_sizes, int n_in,
                              void* d_out, int out_size) {
    const float* F      = (const float*)d_in[0];
    const int*   bidx   = (const int*)d_in[1];
    const int*   nbr    = (const int*)d_in[2];
    const float* W1     = (const float*)d_in[3];
    const float* b1     = (const float*)d_in[4];
    const float* W2     = (const float*)d_in[5];
    const float* b2     = (const float*)d_in[6];
    const float* conv_w = (const float*)d_in[7];
    float* out = (float*)d_out;
    int n = in_sizes[1];   // batch_idx length = N

    k_seg<<<444, 512>>>(F, bidx, n);
    k_gate<<<1, 128>>>(W1, b1, W2, b2);
    k_sm<<<1184, 256>>>(F, bidx, n);
    k_conv<<<(n + 255) / 256, 256>>>(nbr, conv_w, n);

    long total4 = (long)n * (INC / 4);
    k_mul<<<(int)((total4 + 255) / 256), 256>>>(F, bidx, out, n);
}

// round 9
// speedup vs baseline: 2.2220x; 1.0036x over previous
#include <cuda_runtime.h>
#include <math.h>
#include <stdint.h>

#define INC 64
#define HID 16
#define BATCHES 8
#define NMAX 300032   // N=300000 (+ pad row)

// ---- scratch (zero-initialized at module load; k_gate re-zeros after use) ----
__device__ float    g_segsum[BATCHES * INC];
__device__ unsigned g_segmax[BATCHES * INC];   // order-encoded float; 0 == identity
__device__ float    g_count[BATCHES];
__device__ float    g_gate[BATCHES * INC];
__device__ float2   g_sm[NMAX];                // (mean, max) per point, + zero pad row
__device__ float    g_sig[NMAX];               // spatial sigmoid per point

__device__ __forceinline__ unsigned encode_ord(float f) {
    unsigned b = __float_as_uint(f);
    return (b & 0x80000000u) ? ~b : (b ^ 0x80000000u);
}
__device__ __forceinline__ float decode_ord(unsigned u) {
    unsigned b = (u & 0x80000000u) ? (u ^ 0x80000000u) : ~u;
    return __uint_as_float(b);
}

__device__ __forceinline__ void accum4(float4& sum, float4& mx, float4 v) {
    sum.x += v.x; sum.y += v.y; sum.z += v.z; sum.w += v.w;
    mx.x = fmaxf(mx.x, v.x); mx.y = fmaxf(mx.y, v.y);
    mx.z = fmaxf(mx.z, v.z); mx.w = fmaxf(mx.w, v.w);
}

__device__ __forceinline__ void flush_seg(float* s_sum, unsigned* s_max, float* s_cnt,
                                          int cur, int q, float4& sum, float4& mx,
                                          float& cnt) {
    float*    ss = &s_sum[cur * INC + q * 4];
    unsigned* sx = &s_max[cur * INC + q * 4];
    atomicAdd(ss + 0, sum.x); atomicAdd(ss + 1, sum.y);
    atomicAdd(ss + 2, sum.z); atomicAdd(ss + 3, sum.w);
    atomicMax(sx + 0, encode_ord(mx.x)); atomicMax(sx + 1, encode_ord(mx.y));
    atomicMax(sx + 2, encode_ord(mx.z)); atomicMax(sx + 3, encode_ord(mx.w));
    if (q == 0) atomicAdd(&s_cnt[cur], cnt);
    sum = make_float4(0.f, 0.f, 0.f, 0.f);
    mx  = make_float4(-INFINITY, -INFINITY, -INFINITY, -INFINITY);
    cnt = 0.f;
}

// ---- K1: segment sum/max, shared staging, 4-row ILP per thread ----
__global__ __launch_bounds__(512) void k_seg(const float* __restrict__ F,
                                             const int* __restrict__ bidx, int n) {
    __shared__ float    s_sum[BATCHES * INC];
    __shared__ unsigned s_max[BATCHES * INC];
    __shared__ float    s_cnt[BATCHES];

    int t = threadIdx.x;
    for (int i = t; i < BATCHES * INC; i += 512) { s_sum[i] = 0.f; s_max[i] = 0u; }
    if (t < BATCHES) s_cnt[t] = 0.f;
    __syncthreads();

    int chunk = (n + gridDim.x - 1) / gridDim.x;
    int start = blockIdx.x * chunk;
    int end   = min(start + chunk, n);

    int q     = t & 15;    // channel quad
    int rlane = t >> 4;    // 0..31

    float4 sum = make_float4(0.f, 0.f, 0.f, 0.f);
    float4 mx  = make_float4(-INFINITY, -INFINITY, -INFINITY, -INFINITY);
    float cnt = 0.f;
    int cur = -1;

    int r = start + rlane * 4;
    for (; r + 3 < end; r += 128) {
        int b0 = bidx[r],     b1 = bidx[r + 1];
        int b2 = bidx[r + 2], b3 = bidx[r + 3];
        float4 v0 = ((const float4*)(F + (long)r * INC))[q];
        float4 v1 = ((const float4*)(F + (long)(r + 1) * INC))[q];
        float4 v2 = ((const float4*)(F + (long)(r + 2) * INC))[q];
        float4 v3 = ((const float4*)(F + (long)(r + 3) * INC))[q];
        if (b0 != cur) {
            if (cur >= 0) flush_seg(s_sum, s_max, s_cnt, cur, q, sum, mx, cnt);
            cur = b0;
        }
        accum4(sum, mx, v0); cnt += 1.f;
        if (b1 != cur) { flush_seg(s_sum, s_max, s_cnt, cur, q, sum, mx, cnt); cur = b1; }
        accum4(sum, mx, v1); cnt += 1.f;
        if (b2 != cur) { flush_seg(s_sum, s_max, s_cnt, cur, q, sum, mx, cnt); cur = b2; }
        accum4(sum, mx, v2); cnt += 1.f;
        if (b3 != cur) { flush_seg(s_sum, s_max, s_cnt, cur, q, sum, mx, cnt); cur = b3; }
        accum4(sum, mx, v3); cnt += 1.f;
    }
    for (int rr = r; rr < end && rr < r + 4; rr++) {   // per-thread tail
        int b0 = bidx[rr];
        float4 v0 = ((const float4*)(F + (long)rr * INC))[q];
        if (b0 != cur) {
            if (cur >= 0) flush_seg(s_sum, s_max, s_cnt, cur, q, sum, mx, cnt);
            cur = b0;
        }
        accum4(sum, mx, v0); cnt += 1.f;
    }
    if (cur >= 0) flush_seg(s_sum, s_max, s_cnt, cur, q, sum, mx, cnt);
    __syncthreads();

    for (int i = t; i < BATCHES * INC; i += 512) {
        int b = i >> 6;
        if (s_cnt[b] > 0.f) {
            atomicAdd(&g_segsum[i], s_sum[i]);
            atomicMax(&g_segmax[i], s_max[i]);
        }
    }
    if (t < BATCHES && s_cnt[t] > 0.f) atomicAdd(&g_count[t], s_cnt[t]);
}

// ---- K2: tiny shared MLP -> per-batch gate; then RESET accumulators ----
__global__ void k_gate(const float* __restrict__ W1, const float* __restrict__ b1,
                       const float* __restrict__ W2, const float* __restrict__ b2) {
    __shared__ float h1a[BATCHES][HID], h1m[BATCHES][HID];
    int t = threadIdx.x;  // 128 threads
    if (t < BATCHES * HID) {
        int b = t / HID, j = t % HID;
        float sa = b1[j], sm = b1[j];
        float inv = 1.f / g_count[b];
        for (int c = 0; c < INC; c++) {
            float w    = W1[c * HID + j];
            float mean = g_segsum[b * INC + c] * inv;
            float mxv  = decode_ord(g_segmax[b * INC + c]);
            sa += mean * w;
            sm += mxv * w;
        }
        h1a[b][j] = fmaxf(sa, 0.f);
        h1m[b][j] = fmaxf(sm, 0.f);
    }
    __syncthreads();
    for (int i = t; i < BATCHES * INC; i += 128) {   // reset for next call
        g_segsum[i] = 0.f;
        g_segmax[i] = 0u;
    }
    if (t < BATCHES) g_count[t] = 0.f;

    for (int t2 = t; t2 < BATCHES * INC; t2 += 128) {
        int b = t2 / INC, c = t2 % INC;
        float s = 2.f * b2[c];
        for (int j = 0; j < HID; j++)
            s += (h1a[b][j] + h1m[b][j]) * W2[j * INC + c];
        g_gate[t2] = 1.f / (1.f + expf(-s));
    }
}

// ---- K3: half-warp-per-row, float4, 2-row unroll ----
__global__ __launch_bounds__(256) void k_sm(const float* __restrict__ F,
                                            const int* __restrict__ bidx, int n) {
    int gtid   = blockIdx.x * blockDim.x + threadIdx.x;
    if (gtid == 0) g_sm[n] = make_float2(0.f, 0.f);   // pad row
    int hw     = gtid >> 4;
    int lane16 = threadIdx.x & 15;
    int nhw    = (gridDim.x * blockDim.x) >> 4;

    int r0 = hw * 2;
    int stride = nhw * 2;
    for (; r0 + 1 < n; r0 += stride) {
        int r1 = r0 + 1;
        int b0 = bidx[r0], b1 = bidx[r1];
        float4 fA = ((const float4*)(F + (long)r0 * INC))[lane16];
        float4 fB = ((const float4*)(F + (long)r1 * INC))[lane16];
        float4 gA = ((const float4*)(g_gate + b0 * INC))[lane16];
        float4 gB = ((const float4*)(g_gate + b1 * INC))[lane16];
        float a0 = fA.x * gA.x, a1 = fA.y * gA.y, a2 = fA.z * gA.z, a3 = fA.w * gA.w;
        float c0 = fB.x * gB.x, c1 = fB.y * gB.y, c2 = fB.z * gB.z, c3 = fB.w * gB.w;
        float sA = (a0 + a1) + (a2 + a3);
        float mA = fmaxf(fmaxf(a0, a1), fmaxf(a2, a3));
        float sB = (c0 + c1) + (c2 + c3);
        float mB = fmaxf(fmaxf(c0, c1), fmaxf(c2, c3));
        #pragma unroll
        for (int o = 8; o > 0; o >>= 1) {
            sA += __shfl_xor_sync(0xffffffffu, sA, o);
            sB += __shfl_xor_sync(0xffffffffu, sB, o);
            mA = fmaxf(mA, __shfl_xor_sync(0xffffffffu, mA, o));
            mB = fmaxf(mB, __shfl_xor_sync(0xffffffffu, mB, o));
        }
        if (lane16 == 0) {
            g_sm[r0] = make_float2(sA * (1.f / 64.f), mA);
            g_sm[r1] = make_float2(sB * (1.f / 64.f), mB);
        }
    }
    if (r0 < n) {   // tail
        int b = bidx[r0];
        float4 f = ((const float4*)(F + (long)r0 * INC))[lane16];
        float4 g = ((const float4*)(g_gate + b * INC))[lane16];
        float z0 = f.x * g.x, z1 = f.y * g.y, z2 = f.z * g.z, z3 = f.w * g.w;
        float s = (z0 + z1) + (z2 + z3);
        float m = fmaxf(fmaxf(z0, z1), fmaxf(z2, z3));
        #pragma unroll
        for (int o = 8; o > 0; o >>= 1) {
            s += __shfl_xor_sync(0xffffffffu, s, o);
            m = fmaxf(m, __shfl_xor_sync(0xffffffffu, m, o));
        }
        if (lane16 == 0) g_sm[r0] = make_float2(s * (1.f / 64.f), m);
    }
}

// ---- K4: thread-per-point 27-gather conv -> sigmoid.
//      nbr staged to 16B-ALIGNED smem; int4 path only when global side aligned. ----
__global__ __launch_bounds__(256) void k_conv(const int* __restrict__ nbr,
                                              const float* __restrict__ conv_w, int n) {
    __shared__ __align__(16) int s_nbr[256 * 27];
    __shared__ float sw[54];
    int t = threadIdx.x;
    if (t < 54) sw[t] = conv_w[t];

    int base = blockIdx.x * 256;
    int cnt  = min(256, n - base);
    long off = (long)base * 27;                 // element offset (multiple of 4)
    const int* src = nbr + off;
    int total = cnt * 27;

    if ((((uintptr_t)src) & 15) == 0) {         // both sides 16B-aligned: vector staging
        int total4 = total >> 2;
        const int4* src4 = (const int4*)src;
        for (int i = t; i < total4; i += 256)
            ((int4*)s_nbr)[i] = __ldcs(src4 + i);   // streaming: keep F in L2
        for (int i = (total4 << 2) + t; i < total; i += 256)
            s_nbr[i] = __ldcs(src + i);
    } else {                                    // scalar coalesced fallback
        for (int i = t; i < total; i += 256)
            s_nbr[i] = __ldcs(src + i);
    }
    __syncthreads();

    if (t < cnt) {
        const int* nb = &s_nbr[t * 27];
        float p = 0.f;
        #pragma unroll
        for (int k = 0; k < 27; k++) {
            float2 s = g_sm[nb[k]];             // L2-resident gather (2.4 MB)
            p += s.x * sw[2 * k] + s.y * sw[2 * k + 1];
        }
        g_sig[base + t] = 1.f / (1.f + expf(-p));
    }
}

// ---- K5: pure float4 stream: out = F * gate[bidx] * sig ----
__global__ void k_mul(const float* __restrict__ F, const int* __restrict__ bidx,
                      float* __restrict__ out, int n) {
    long total = (long)n * (INC / 4);
    long i = (long)blockIdx.x * blockDim.x + threadIdx.x;
    if (i >= total) return;
    int r  = (int)(i >> 4);
    int c4 = (int)(i & 15);
    float4 f = ((const float4*)F)[i];
    int b = bidx[r];
    float4 g = ((const float4*)g_gate)[b * 16 + c4];
    float sg = g_sig[r];
    float4 o;
    o.x = f.x * g.x * sg; o.y = f.y * g.y * sg;
    o.z = f.z * g.z * sg; o.w = f.w * g.w * sg;
    __stcs((float4*)out + i, o);
}

extern "C" void kernel_launch(void* const* d_in, const int* in_sizes, int n_in,
                              void* d_out, int out_size) {
    const float* F      = (const float*)d_in[0];
    const int*   bidx   = (const int*)d_in[1];
    const int*   nbr    = (const int*)d_in[2];
    const float* W1     = (const float*)d_in[3];
    const float* b1     = (const float*)d_in[4];
    const float* W2     = (const float*)d_in[5];
    const float* b2     = (const float*)d_in[6];
    const float* conv_w = (const float*)d_in[7];
    float* out = (float*)d_out;
    int n = in_sizes[1];   // batch_idx length = N

    k_seg<<<444, 512>>>(F, bidx, n);
    k_gate<<<1, 128>>>(W1, b1, W2, b2);
    k_sm<<<1184, 256>>>(F, bidx, n);
    k_conv<<<(n + 255) / 256, 256>>>(nbr, conv_w, n);

    long total4 = (long)n * (INC / 4);
    k_mul<<<(int)((total4 + 255) / 256), 256>>>(F, bidx, out, n);
}

// round 10
// speedup vs baseline: 2.2300x; 1.0036x over previous
#include <cuda_runtime.h>
#include <math.h>
#include <stdint.h>

#define INC 64
#define HID 16
#define BATCHES 8
#define NMAX 300032   // N=300000 (+ pad row)

// ---- scratch (zero-initialized at module load; k_gate re-zeros after use) ----
__device__ float    g_segsum[BATCHES * INC];
__device__ unsigned g_segmax[BATCHES * INC];   // order-encoded float; 0 == identity
__device__ float    g_count[BATCHES];
__device__ float    g_gate[BATCHES * INC];
__device__ float2   g_sm[NMAX];                // (mean, max) per point, + zero pad row
__device__ float    g_sig[NMAX];               // spatial sigmoid per point

__device__ __forceinline__ unsigned encode_ord(float f) {
    unsigned b = __float_as_uint(f);
    return (b & 0x80000000u) ? ~b : (b ^ 0x80000000u);
}
__device__ __forceinline__ float decode_ord(unsigned u) {
    unsigned b = (u & 0x80000000u) ? (u ^ 0x80000000u) : ~u;
    return __uint_as_float(b);
}

__device__ __forceinline__ void accum4(float4& sum, float4& mx, float4 v) {
    sum.x += v.x; sum.y += v.y; sum.z += v.z; sum.w += v.w;
    mx.x = fmaxf(mx.x, v.x); mx.y = fmaxf(mx.y, v.y);
    mx.z = fmaxf(mx.z, v.z); mx.w = fmaxf(mx.w, v.w);
}

__device__ __forceinline__ void flush_seg(float* s_sum, unsigned* s_max, float* s_cnt,
                                          int cur, int q, float4& sum, float4& mx,
                                          float& cnt) {
    float*    ss = &s_sum[cur * INC + q * 4];
    unsigned* sx = &s_max[cur * INC + q * 4];
    atomicAdd(ss + 0, sum.x); atomicAdd(ss + 1, sum.y);
    atomicAdd(ss + 2, sum.z); atomicAdd(ss + 3, sum.w);
    atomicMax(sx + 0, encode_ord(mx.x)); atomicMax(sx + 1, encode_ord(mx.y));
    atomicMax(sx + 2, encode_ord(mx.z)); atomicMax(sx + 3, encode_ord(mx.w));
    if (q == 0) atomicAdd(&s_cnt[cur], cnt);
    sum = make_float4(0.f, 0.f, 0.f, 0.f);
    mx  = make_float4(-INFINITY, -INFINITY, -INFINITY, -INFINITY);
    cnt = 0.f;
}

// ---- K1: segment sum/max, shared staging, 4-row ILP per thread ----
__global__ __launch_bounds__(512) void k_seg(const float* __restrict__ F,
                                             const int* __restrict__ bidx, int n) {
    __shared__ float    s_sum[BATCHES * INC];
    __shared__ unsigned s_max[BATCHES * INC];
    __shared__ float    s_cnt[BATCHES];

    int t = threadIdx.x;
    for (int i = t; i < BATCHES * INC; i += 512) { s_sum[i] = 0.f; s_max[i] = 0u; }
    if (t < BATCHES) s_cnt[t] = 0.f;
    __syncthreads();

    int chunk = (n + gridDim.x - 1) / gridDim.x;
    int start = blockIdx.x * chunk;
    int end   = min(start + chunk, n);

    int q     = t & 15;    // channel quad
    int rlane = t >> 4;    // 0..31

    float4 sum = make_float4(0.f, 0.f, 0.f, 0.f);
    float4 mx  = make_float4(-INFINITY, -INFINITY, -INFINITY, -INFINITY);
    float cnt = 0.f;
    int cur = -1;

    int r = start + rlane * 4;
    for (; r + 3 < end; r += 128) {
        int b0 = bidx[r],     b1 = bidx[r + 1];
        int b2 = bidx[r + 2], b3 = bidx[r + 3];
        float4 v0 = ((const float4*)(F + (long)r * INC))[q];
        float4 v1 = ((const float4*)(F + (long)(r + 1) * INC))[q];
        float4 v2 = ((const float4*)(F + (long)(r + 2) * INC))[q];
        float4 v3 = ((const float4*)(F + (long)(r + 3) * INC))[q];
        if (b0 != cur) {
            if (cur >= 0) flush_seg(s_sum, s_max, s_cnt, cur, q, sum, mx, cnt);
            cur = b0;
        }
        accum4(sum, mx, v0); cnt += 1.f;
        if (b1 != cur) { flush_seg(s_sum, s_max, s_cnt, cur, q, sum, mx, cnt); cur = b1; }
        accum4(sum, mx, v1); cnt += 1.f;
        if (b2 != cur) { flush_seg(s_sum, s_max, s_cnt, cur, q, sum, mx, cnt); cur = b2; }
        accum4(sum, mx, v2); cnt += 1.f;
        if (b3 != cur) { flush_seg(s_sum, s_max, s_cnt, cur, q, sum, mx, cnt); cur = b3; }
        accum4(sum, mx, v3); cnt += 1.f;
    }
    for (int rr = r; rr < end && rr < r + 4; rr++) {   // per-thread tail
        int b0 = bidx[rr];
        float4 v0 = ((const float4*)(F + (long)rr * INC))[q];
        if (b0 != cur) {
            if (cur >= 0) flush_seg(s_sum, s_max, s_cnt, cur, q, sum, mx, cnt);
            cur = b0;
        }
        accum4(sum, mx, v0); cnt += 1.f;
    }
    if (cur >= 0) flush_seg(s_sum, s_max, s_cnt, cur, q, sum, mx, cnt);
    __syncthreads();

    for (int i = t; i < BATCHES * INC; i += 512) {
        int b = i >> 6;
        if (s_cnt[b] > 0.f) {
            atomicAdd(&g_segsum[i], s_sum[i]);
            atomicMax(&g_segmax[i], s_max[i]);
        }
    }
    if (t < BATCHES && s_cnt[t] > 0.f) atomicAdd(&g_count[t], s_cnt[t]);
}

// ---- K2: tiny shared MLP -> per-batch gate; then RESET accumulators ----
__global__ void k_gate(const float* __restrict__ W1, const float* __restrict__ b1,
                       const float* __restrict__ W2, const float* __restrict__ b2) {
    __shared__ float h1a[BATCHES][HID], h1m[BATCHES][HID];
    int t = threadIdx.x;  // 128 threads
    if (t < BATCHES * HID) {
        int b = t / HID, j = t % HID;
        float sa = b1[j], sm = b1[j];
        float inv = 1.f / g_count[b];
        for (int c = 0; c < INC; c++) {
            float w    = W1[c * HID + j];
            float mean = g_segsum[b * INC + c] * inv;
            float mxv  = decode_ord(g_segmax[b * INC + c]);
            sa += mean * w;
            sm += mxv * w;
        }
        h1a[b][j] = fmaxf(sa, 0.f);
        h1m[b][j] = fmaxf(sm, 0.f);
    }
    __syncthreads();
    for (int i = t; i < BATCHES * INC; i += 128) {   // reset for next call
        g_segsum[i] = 0.f;
        g_segmax[i] = 0u;
    }
    if (t < BATCHES) g_count[t] = 0.f;

    for (int t2 = t; t2 < BATCHES * INC; t2 += 128) {
        int b = t2 / INC, c = t2 % INC;
        float s = 2.f * b2[c];
        for (int j = 0; j < HID; j++)
            s += (h1a[b][j] + h1m[b][j]) * W2[j * INC + c];
        g_gate[t2] = 1.f / (1.f + expf(-s));
    }
}

// ---- K3: half-warp-per-row, float4, 2-row unroll ----
__global__ __launch_bounds__(256) void k_sm(const float* __restrict__ F,
                                            const int* __restrict__ bidx, int n) {
    int gtid   = blockIdx.x * blockDim.x + threadIdx.x;
    if (gtid == 0) g_sm[n] = make_float2(0.f, 0.f);   // pad row
    int hw     = gtid >> 4;
    int lane16 = threadIdx.x & 15;
    int nhw    = (gridDim.x * blockDim.x) >> 4;

    int r0 = hw * 2;
    int stride = nhw * 2;
    for (; r0 + 1 < n; r0 += stride) {
        int r1 = r0 + 1;
        int b0 = bidx[r0], b1 = bidx[r1];
        float4 fA = ((const float4*)(F + (long)r0 * INC))[lane16];
        float4 fB = ((const float4*)(F + (long)r1 * INC))[lane16];
        float4 gA = ((const float4*)(g_gate + b0 * INC))[lane16];
        float4 gB = ((const float4*)(g_gate + b1 * INC))[lane16];
        float a0 = fA.x * gA.x, a1 = fA.y * gA.y, a2 = fA.z * gA.z, a3 = fA.w * gA.w;
        float c0 = fB.x * gB.x, c1 = fB.y * gB.y, c2 = fB.z * gB.z, c3 = fB.w * gB.w;
        float sA = (a0 + a1) + (a2 + a3);
        float mA = fmaxf(fmaxf(a0, a1), fmaxf(a2, a3));
        float sB = (c0 + c1) + (c2 + c3);
        float mB = fmaxf(fmaxf(c0, c1), fmaxf(c2, c3));
        #pragma unroll
        for (int o = 8; o > 0; o >>= 1) {
            sA += __shfl_xor_sync(0xffffffffu, sA, o);
            sB += __shfl_xor_sync(0xffffffffu, sB, o);
            mA = fmaxf(mA, __shfl_xor_sync(0xffffffffu, mA, o));
            mB = fmaxf(mB, __shfl_xor_sync(0xffffffffu, mB, o));
        }
        if (lane16 == 0) {
            g_sm[r0] = make_float2(sA * (1.f / 64.f), mA);
            g_sm[r1] = make_float2(sB * (1.f / 64.f), mB);
        }
    }
    if (r0 < n) {   // tail
        int b = bidx[r0];
        float4 f = ((const float4*)(F + (long)r0 * INC))[lane16];
        float4 g = ((const float4*)(g_gate + b * INC))[lane16];
        float z0 = f.x * g.x, z1 = f.y * g.y, z2 = f.z * g.z, z3 = f.w * g.w;
        float s = (z0 + z1) + (z2 + z3);
        float m = fmaxf(fmaxf(z0, z1), fmaxf(z2, z3));
        #pragma unroll
        for (int o = 8; o > 0; o >>= 1) {
            s += __shfl_xor_sync(0xffffffffu, s, o);
            m = fmaxf(m, __shfl_xor_sync(0xffffffffu, m, o));
        }
        if (lane16 == 0) g_sm[r0] = make_float2(s * (1.f / 64.f), m);
    }
}

// ---- K4: warp-autonomous 27-gather conv -> sigmoid.
//      Each warp stages its own 32 points x 27 nbr, __syncwarp only. ----
__global__ __launch_bounds__(512) void k_conv(const int* __restrict__ nbr,
                                              const float* __restrict__ conv_w, int n) {
    __shared__ __align__(16) int s_nbr[16][32 * 27];   // per-warp slice (3456 B each)
    int t = threadIdx.x;
    int w = t >> 5, lane = t & 31;

    int wbase = blockIdx.x * 512 + w * 32;              // first point of this warp
    if (wbase >= n) return;
    int wcnt = min(32, n - wbase);
    int total = wcnt * 27;
    const int* src = nbr + (long)wbase * 27;
    int* dst = s_nbr[w];

    if ((((uintptr_t)src) & 15) == 0) {                 // vector staging
        int total4 = total >> 2;
        const int4* src4 = (const int4*)src;
        for (int i = lane; i < total4; i += 32)
            ((int4*)dst)[i] = __ldcs(src4 + i);         // streaming: keep F in L2
        for (int i = (total4 << 2) + lane; i < total; i += 32)
            dst[i] = __ldcs(src + i);
    } else {                                            // scalar coalesced fallback
        for (int i = lane; i < total; i += 32)
            dst[i] = __ldcs(src + i);
    }
    __syncwarp();

    if (lane < wcnt) {
        const int* nb = dst + lane * 27;
        float p = 0.f;
        #pragma unroll
        for (int k = 0; k < 27; k++) {
            float2 s = g_sm[nb[k]];                     // L2-resident gather (2.4 MB)
            p += s.x * __ldg(conv_w + 2 * k) + s.y * __ldg(conv_w + 2 * k + 1);
        }
        g_sig[wbase + lane] = 1.f / (1.f + expf(-p));
    }
}

// ---- K5: pure float4 stream: out = F * gate[bidx] * sig ----
__global__ void k_mul(const float* __restrict__ F, const int* __restrict__ bidx,
                      float* __restrict__ out, int n) {
    long total = (long)n * (INC / 4);
    long i = (long)blockIdx.x * blockDim.x + threadIdx.x;
    if (i >= total) return;
    int r  = (int)(i >> 4);
    int c4 = (int)(i & 15);
    float4 f = ((const float4*)F)[i];
    int b = bidx[r];
    float4 g = ((const float4*)g_gate)[b * 16 + c4];
    float sg = g_sig[r];
    float4 o;
    o.x = f.x * g.x * sg; o.y = f.y * g.y * sg;
    o.z = f.z * g.z * sg; o.w = f.w * g.w * sg;
    __stcs((float4*)out + i, o);
}

extern "C" void kernel_launch(void* const* d_in, const int* in_sizes, int n_in,
                              void* d_out, int out_size) {
    const float* F      = (const float*)d_in[0];
    const int*   bidx   = (const int*)d_in[1];
    const int*   nbr    = (const int*)d_in[2];
    const float* W1     = (const float*)d_in[3];
    const float* b1     = (const float*)d_in[4];
    const float* W2     = (const float*)d_in[5];
    const float* b2     = (const float*)d_in[6];
    const float* conv_w = (const float*)d_in[7];
    float* out = (float*)d_out;
    int n = in_sizes[1];   // batch_idx length = N

    k_seg<<<592, 512>>>(F, bidx, n);                    // 4 blocks/SM -> 100% occ
    k_gate<<<1, 128>>>(W1, b1, W2, b2);
    k_sm<<<1184, 256>>>(F, bidx, n);
    k_conv<<<(n + 511) / 512, 512>>>(nbr, conv_w, n);

    long total4 = (long)n * (INC / 4);
    k_mul<<<(int)((total4 + 255) / 256), 256>>>(F, bidx, out, n);
}